// round 14
// baseline (speedup 1.0000x reference)
#include <cuda_runtime.h>
#include <cuda_bf16.h>
#include <cuda_fp16.h>
#include <cstdint>
#include <cstddef>

// Problem sizes (fixed by the reference)
constexpr int M  = 8192;    // batch
constexpr int N  = 16384;   // d_sae
constexpr int KD = 1024;    // d_in
constexpr int TOPK = 32;
constexpr int NCAND = 48;   // candidate pool for exact refinement
constexpr float TAU = 4e-3f;  // boundary gap threshold (fp16 scan noise)

// Output layout: [x_hat (M*KD), h_sparse (M*N), recon_loss, l0]
constexpr size_t OFF_H    = (size_t)M * KD;
constexpr size_t OFF_LOSS = OFF_H + (size_t)M * N;

// Scratch: control state + transposed W copies (96 MB total; proven-safe regime)
__device__ float g_val[M * TOPK];
__device__ int   g_idx[M * TOPK];
__device__ float g_loss_sum;
__device__ int   g_pos_count;
__device__ int   g_w0_is_enc;
__device__ __align__(16) __half g_wt_f16[(size_t)N * KD];   // 32 MB, W_enc^T [N][KD]
__device__ __align__(16) float  g_wt_f32[(size_t)N * KD];   // 64 MB, W_enc^T [N][KD]

// ---------------------------------------------------------------------------
// Helpers (sm_80-compatible PTX only: mma.sync + cp.async + ldmatrix)
// ---------------------------------------------------------------------------
__device__ __forceinline__ void mma_fp16(float* c, const uint32_t* a, const uint32_t* b) {
    asm volatile(
        "mma.sync.aligned.m16n8k16.row.col.f32.f16.f16.f32 "
        "{%0,%1,%2,%3}, {%4,%5,%6,%7}, {%8,%9}, {%0,%1,%2,%3};\n"
        : "+f"(c[0]), "+f"(c[1]), "+f"(c[2]), "+f"(c[3])
        : "r"(a[0]), "r"(a[1]), "r"(a[2]), "r"(a[3]), "r"(b[0]), "r"(b[1]));
}
__device__ __forceinline__ void cp_async16(uint32_t saddr, const void* gptr) {
    asm volatile("cp.async.ca.shared.global [%0], [%1], 16;" :: "r"(saddr), "l"(gptr));
}
#define CP_COMMIT()  asm volatile("cp.async.commit_group;" ::: "memory")
#define CP_WAIT(n)   asm volatile("cp.async.wait_group %0;" :: "n"(n) : "memory")
__device__ __forceinline__ void ldmx4(uint32_t* r, uint32_t addr) {
    asm volatile("ldmatrix.sync.aligned.m8n8.x4.shared.b16 {%0,%1,%2,%3}, [%4];"
        : "=r"(r[0]), "=r"(r[1]), "=r"(r[2]), "=r"(r[3]) : "r"(addr));
}

// ---------------------------------------------------------------------------
// Kernel D: decide which 16.7M tensor is W_enc; reset accumulators.
// ---------------------------------------------------------------------------
__global__ void detect_kernel(const float* __restrict__ w0,
                              const float* __restrict__ w1) {
    __shared__ float s0[256], s1[256];
    const int tid = threadIdx.x;
    float m0 = 0.f, m1 = 0.f;
    for (int i = tid; i < 8192; i += 256) {
        m0 = fmaxf(m0, fabsf(w0[i]));
        m1 = fmaxf(m1, fabsf(w1[i]));
    }
    s0[tid] = m0; s1[tid] = m1;
    __syncthreads();
    #pragma unroll
    for (int s = 128; s > 0; s >>= 1) {
        if (tid < s) {
            s0[tid] = fmaxf(s0[tid], s0[tid + s]);
            s1[tid] = fmaxf(s1[tid], s1[tid + s]);
        }
        __syncthreads();
    }
    if (tid == 0) {
        g_w0_is_enc = (s0[0] > s1[0]) ? 1 : 0;
        g_loss_sum  = 0.f;
        g_pos_count = 0;
    }
}

// ---------------------------------------------------------------------------
// Kernel C1: x fp32 -> fp16, stored in the x_hat region of d_out.
// ---------------------------------------------------------------------------
__global__ void convert_x_kernel(const float* __restrict__ x,
                                 __half* __restrict__ xh) {
    const size_t i = ((size_t)blockIdx.x * 256 + threadIdx.x) * 8;
    float4 v0 = *(const float4*)(x + i);
    float4 v1 = *(const float4*)(x + i + 4);
    __half2 h[4];
    h[0] = __floats2half2_rn(v0.x, v0.y);
    h[1] = __floats2half2_rn(v0.z, v0.w);
    h[2] = __floats2half2_rn(v1.x, v1.y);
    h[3] = __floats2half2_rn(v1.z, v1.w);
    *(uint4*)(xh + i) = *(uint4*)h;
}

// ---------------------------------------------------------------------------
// Kernel C2: transpose W_enc [KD][N] -> g_wt_f16 and g_wt_f32 [N][KD].
// ---------------------------------------------------------------------------
__global__ void convert_w_kernel(const float* __restrict__ W0,
                                 const float* __restrict__ W1) {
    __shared__ float tile[32][33];
    const float* __restrict__ W = g_w0_is_enc ? W0 : W1;   // W_enc [KD][N]
    const int n0 = blockIdx.x * 32;
    const int k0 = blockIdx.y * 32;
    const int tx = threadIdx.x & 31;
    const int ty = threadIdx.x >> 5;     // 0..7
    #pragma unroll
    for (int i = 0; i < 4; i++) {
        const int kr = ty + i * 8;
        tile[kr][tx] = W[(size_t)(k0 + kr) * N + n0 + tx];
    }
    __syncthreads();
    #pragma unroll
    for (int i = 0; i < 4; i++) {
        const int nr = ty + i * 8;
        const float f = tile[tx][nr];
        g_wt_f16[(size_t)(n0 + nr) * KD + k0 + tx] = __float2half_rn(f);
        g_wt_f32[(size_t)(n0 + nr) * KD + k0 + tx] = f;
    }
}

// ---------------------------------------------------------------------------
// Kernel 1: encoder GEMM, single-pass fp16 HMMA, fp32 accumulate.
// EXACT R12 configuration (proven fastest: 1.035 ms): CTA 128x128, 8 warps
// (2x4), warp tile 64x32, k16 chunks, 2-stage cp.async, 1 sync/chunk,
// 24 KB static smem, 2 CTAs/SM.
// ---------------------------------------------------------------------------
constexpr uint32_t SOFF_A = 0, SOFF_B = 6144;
constexpr uint32_t BUFSZ = 12288;

__global__ void __launch_bounds__(256, 2) enc_gemm_hmma(
    const __half* __restrict__ xh,   // [M][KD]
    const float* __restrict__ be,
    float* __restrict__ C)
{
    __shared__ __align__(16) uint8_t smraw[2 * BUFSZ];   // 24 KB static

    const int tid  = threadIdx.x;
    const int warp = tid >> 5;
    const int lane = tid & 31;
    const int g    = lane >> 2;
    const int t    = lane & 3;
    const int wm   = warp >> 2;      // 0..1 -> M 64-half
    const int wn   = warp & 3;       // 0..3 -> N 32-quarter
    const int rowBase = blockIdx.y * 128;
    const int colBase = blockIdx.x * 128;
    const uint32_t sb = (uint32_t)__cvta_generic_to_shared(smraw);

    const int ldrow = tid >> 1;
    const int ldseg = tid & 1;
    const uint32_t dstOff = (uint32_t)ldrow * 48 + (uint32_t)ldseg * 16;
    const size_t aSrc = (size_t)(rowBase + ldrow) * KD + ldseg * 8;
    const size_t bSrc = (size_t)(colBase + ldrow) * KD + ldseg * 8;

    const uint32_t aFragOff = (uint32_t)(wm * 64 + (lane & 15)) * 48 + ((lane >> 4) * 16);
    const uint32_t bFragOff = (uint32_t)(wn * 32 + (lane & 15)) * 48 + ((lane >> 4) * 16);

    float acc[4][4][4];
    #pragma unroll
    for (int i = 0; i < 4; i++)
        #pragma unroll
        for (int j = 0; j < 4; j++)
            #pragma unroll
            for (int e = 0; e < 4; e++) acc[i][j][e] = 0.f;

    auto issue = [&](int k0, int buf) {
        const uint32_t b = sb + (uint32_t)buf * BUFSZ;
        cp_async16(b + SOFF_A + dstOff, xh + aSrc + k0);
        cp_async16(b + SOFF_B + dstOff, g_wt_f16 + bSrc + k0);
        CP_COMMIT();
    };

    issue(0, 0);
    #pragma unroll 1
    for (int ic = 0; ic < KD / 16; ic++) {
        CP_WAIT(0);
        __syncthreads();
        if (ic < KD / 16 - 1)
            issue((ic + 1) * 16, (ic + 1) & 1);

        const uint32_t bb = sb + (uint32_t)(ic & 1) * BUFSZ;
        uint32_t ah[4][4], bh[2][4];
        #pragma unroll
        for (int mf = 0; mf < 4; mf++)
            ldmx4(ah[mf], bb + SOFF_A + aFragOff + mf * 768);
        #pragma unroll
        for (int b2 = 0; b2 < 2; b2++)
            ldmx4(bh[b2], bb + SOFF_B + bFragOff + b2 * 768);

        #pragma unroll
        for (int mf = 0; mf < 4; mf++) {
            #pragma unroll
            for (int b2 = 0; b2 < 2; b2++) {
                uint32_t b0[2] = { bh[b2][0], bh[b2][2] };
                uint32_t b1[2] = { bh[b2][1], bh[b2][3] };
                mma_fp16(acc[mf][2 * b2 + 0], ah[mf], b0);
                mma_fp16(acc[mf][2 * b2 + 1], ah[mf], b1);
            }
        }
    }

    // Epilogue: bias + relu + store
    #pragma unroll
    for (int mf = 0; mf < 4; mf++) {
        const int row = rowBase + wm * 64 + mf * 16 + g;
        #pragma unroll
        for (int b2 = 0; b2 < 2; b2++) {
            #pragma unroll
            for (int j = 0; j < 2; j++) {
                const int col = colBase + wn * 32 + b2 * 16 + j * 8 + 2 * t;
                const float* a = acc[mf][2 * b2 + j];
                const float2 bv = *(const float2*)(be + col);
                float2 o0, o1;
                o0.x = fmaxf(a[0] + bv.x, 0.f);
                o0.y = fmaxf(a[1] + bv.y, 0.f);
                o1.x = fmaxf(a[2] + bv.x, 0.f);
                o1.y = fmaxf(a[3] + bv.y, 0.f);
                *(float2*)(C + (size_t)row * N + col)       = o0;
                *(float2*)(C + (size_t)(row + 8) * N + col) = o1;
            }
        }
    }
}

// ---------------------------------------------------------------------------
// Kernel 2: per-row top-32, warp-per-row, REGISTER-RESIDENT candidate lists.
// Scan keeps per-lane top-8 (value,index) sorted in registers. Extraction =
// 48 warp shuffle-argmaxes over lane heads + register shift pop — no memory
// rescans (R12 burned ~790 MB of latency-chained reads there). If a lane is
// asked for its 9th element (P~1e-5/lane), fallback rescans that lane's
// intact segment for the next element in (v desc, idx asc) order after the
// last popped — exact. Then fp64 refinement (TAU gate) + zero + scatter.
// ---------------------------------------------------------------------------
__global__ __launch_bounds__(256) void topk_kernel(
    float* __restrict__ hsp,
    const float* __restrict__ x,
    const float* __restrict__ be)
{
    __shared__ float  s_cv[8][NCAND];
    __shared__ int    s_ci[8][NCAND];
    __shared__ double s_rv[8][NCAND];
    __shared__ int    s_keep[8][TOPK];

    const int w    = threadIdx.x >> 5;
    const int lane = threadIdx.x & 31;
    const int row  = blockIdx.x * 8 + w;
    float* pre = hsp + (size_t)row * N;

    // ---- scan: per-lane top-8 sorted descending by (v, then lower idx) ----
    float rv[8]; int ri[8];
    #pragma unroll
    for (int p = 0; p < 8; p++) { rv[p] = -1.f; ri[p] = 1 << 30; }

    auto ins = [&](float v, int i) {
        if (v > rv[7] || (v == rv[7] && i < ri[7])) {
            rv[7] = v; ri[7] = i;
            #pragma unroll
            for (int p = 7; p > 0; p--) {
                bool sw = (rv[p] > rv[p - 1]) ||
                          (rv[p] == rv[p - 1] && ri[p] < ri[p - 1]);
                if (sw) {
                    float tv = rv[p]; rv[p] = rv[p - 1]; rv[p - 1] = tv;
                    int   ti = ri[p]; ri[p] = ri[p - 1]; ri[p - 1] = ti;
                }
            }
        }
    };

    #pragma unroll 4
    for (int j = 0; j < 128; j++) {
        const int gi = (j * 32 + lane) * 4;
        float4 v = *(const float4*)(pre + gi);
        ins(v.x, gi); ins(v.y, gi + 1); ins(v.z, gi + 2); ins(v.w, gi + 3);
    }

    // ---- extraction: 48 pops, all in registers ----
    float lastV = 0.f; int lastI = 0;
    for (int it = 0; it < NCAND; it++) {
        if (ri[0] == (1 << 30)) {
            // ultra-rare refill: next element after (lastV, lastI) in order
            float nv = -1.f; int ni = 1 << 30;
            for (int j = 0; j < 128; j++) {
                const int gi = (j * 32 + lane) * 4;
                float4 v = *(const float4*)(pre + gi);
                const float vs[4] = { v.x, v.y, v.z, v.w };
                #pragma unroll
                for (int e = 0; e < 4; e++) {
                    const float vv = vs[e]; const int ii = gi + e;
                    const bool after = (vv < lastV) || (vv == lastV && ii > lastI);
                    if (after && (vv > nv || (vv == nv && ii < ni))) { nv = vv; ni = ii; }
                }
            }
            rv[0] = nv; ri[0] = ni;
        }

        float bv = rv[0]; int bi = ri[0];
        #pragma unroll
        for (int s = 16; s; s >>= 1) {
            float ov = __shfl_xor_sync(0xffffffffu, bv, s);
            int   oi = __shfl_xor_sync(0xffffffffu, bi, s);
            if (ov > bv || (ov == bv && oi < bi)) { bv = ov; bi = oi; }
        }
        if (lane == 0) { s_cv[w][it] = bv; s_ci[w][it] = bi; }

        const int wl = (bi >> 2) & 31;      // lane owning the winner
        if (lane == wl) {
            lastV = rv[0]; lastI = ri[0];
            #pragma unroll
            for (int p = 0; p < 7; p++) { rv[p] = rv[p + 1]; ri[p] = ri[p + 1]; }
            rv[7] = -1.f; ri[7] = 1 << 30;
        }
    }
    __syncwarp();

    // ---- boundary gate + fp64 exact refinement ----
    const float gap = s_cv[w][TOPK - 1] - s_cv[w][TOPK];
    if (gap < TAU) {
        const float* xr = x + (size_t)row * KD;
        for (int c = 0; c < NCAND; c++) {
            const int idx = s_ci[w][c];
            const float* wr = g_wt_f32 + (size_t)idx * KD;
            double s = 0.0;
            for (int k = lane; k < KD; k += 32)
                s += (double)xr[k] * (double)wr[k];
            #pragma unroll
            for (int sh = 16; sh; sh >>= 1)
                s += __shfl_xor_sync(0xffffffffu, s, sh);
            if (lane == 0) s_rv[w][c] = s + (double)be[idx];
        }
        __syncwarp();
        if (lane == 0) {
            int cnt = 0;
            for (int c = 0; c < NCAND && cnt < TOPK; c++) {
                int rank = 0;
                const double vc = s_rv[w][c];
                const int ic = s_ci[w][c];
                for (int d = 0; d < NCAND; d++) {
                    const double vd = s_rv[w][d];
                    if (vd > vc || (vd == vc && s_ci[w][d] < ic)) rank++;
                }
                if (rank < TOPK) s_keep[w][cnt++] = c;
            }
            for (; cnt < TOPK; cnt++) s_keep[w][cnt] = cnt;
        }
    } else if (lane == 0) {
        #pragma unroll
        for (int i = 0; i < TOPK; i++) s_keep[w][i] = i;
    }
    __syncwarp();

    // ---- zero the row, scatter the kept 32 ----
    const float4 z4 = make_float4(0.f, 0.f, 0.f, 0.f);
    #pragma unroll 4
    for (int j = 0; j < 128; j++) {
        int gi = (j * 32 + lane) * 4;
        *(float4*)(pre + gi) = z4;
    }
    __syncwarp();
    if (lane == 0) {
        int pos = 0;
        #pragma unroll
        for (int i = 0; i < TOPK; i++) {
            const int c = s_keep[w][i];
            const float v = s_cv[w][c];
            const int idx = s_ci[w][c];
            pre[idx] = v;
            g_val[row * TOPK + i] = v;
            g_idx[row * TOPK + i] = idx;
            if (v > 0.f) pos++;
        }
        atomicAdd(&g_pos_count, pos);
    }
}

// ---------------------------------------------------------------------------
// Kernel 3: sparse decoder + squared-error accumulation (unchanged)
// ---------------------------------------------------------------------------
__global__ __launch_bounds__(256) void decoder_kernel(
    const float* __restrict__ x,
    const float* __restrict__ W0,
    const float* __restrict__ W1,
    const float* __restrict__ bd,
    float* __restrict__ xhat)
{
    const float* __restrict__ Wd = g_w0_is_enc ? W1 : W0;   // W_dec [N, KD]

    __shared__ float sv[TOPK];
    __shared__ int   si[TOPK];
    __shared__ float red[256];

    const int row = blockIdx.x;
    const int tid = threadIdx.x;
    if (tid < TOPK) {
        sv[tid] = g_val[row * TOPK + tid];
        si[tid] = g_idx[row * TOPK + tid];
    }
    __syncthreads();

    const int d = tid * 4;
    float4 acc = *(const float4*)(bd + d);
    #pragma unroll 4
    for (int j = 0; j < TOPK; j++) {
        float v = sv[j];
        float4 wv = *(const float4*)(Wd + (size_t)si[j] * KD + d);
        acc.x = fmaf(v, wv.x, acc.x);
        acc.y = fmaf(v, wv.y, acc.y);
        acc.z = fmaf(v, wv.z, acc.z);
        acc.w = fmaf(v, wv.w, acc.w);
    }
    *(float4*)(xhat + (size_t)row * KD + d) = acc;

    float4 xv = *(const float4*)(x + (size_t)row * KD + d);
    float ex = acc.x - xv.x, ey = acc.y - xv.y;
    float ez = acc.z - xv.z, ew = acc.w - xv.w;
    red[tid] = ex * ex + ey * ey + ez * ez + ew * ew;
    __syncthreads();
    #pragma unroll
    for (int s = 128; s > 0; s >>= 1) {
        if (tid < s) red[tid] += red[tid + s];
        __syncthreads();
    }
    if (tid == 0) atomicAdd(&g_loss_sum, red[0]);
}

// ---------------------------------------------------------------------------
// Kernel 4: finalize scalars
// ---------------------------------------------------------------------------
__global__ void finalize_kernel(float* __restrict__ scal) {
    scal[0] = g_loss_sum / (float)((size_t)M * KD);
    scal[1] = (float)g_pos_count / (float)M;
}

// ---------------------------------------------------------------------------
extern "C" void kernel_launch(void* const* d_in, const int* in_sizes, int n_in,
                              void* d_out, int out_size) {
    const float* x  = nullptr;
    const float* be = nullptr;
    const float* bd = nullptr;
    const float* w0 = nullptr;
    const float* w1 = nullptr;
    for (int i = 0; i < n_in; i++) {
        const float* p = (const float*)d_in[i];
        const long long s = in_sizes[i];
        if      (s == (long long)M * KD || s == (long long)M * KD * 4) x  = p;
        else if (s == N        || s == (long long)N * 4)               be = p;
        else if (s == KD       || s == (long long)KD * 4)              bd = p;
        else if (s == (long long)KD * N || s == (long long)KD * N * 4) { if (!w0) w0 = p; else w1 = p; }
    }
    if (!x || !be || !bd || !w0 || !w1) {
        x  = (const float*)d_in[0];
        w0 = (const float*)d_in[1];
        be = (const float*)d_in[2];
        w1 = (const float*)d_in[3];
        bd = (const float*)d_in[4];
    }

    float* out  = (float*)d_out;
    float* xhat = out;
    float* hsp  = out + OFF_H;
    float* scal = out + OFF_LOSS;

    // x_f16 lives in the x_hat region until the decoder overwrites it
    __half* xh = (__half*)xhat;

    detect_kernel<<<1, 256>>>(w0, w1);

    convert_x_kernel<<<M * KD / 2048, 256>>>(x, xh);
    convert_w_kernel<<<dim3(N / 32, KD / 32), 256>>>(w0, w1);

    dim3 gGrid(N / 128, M / 128);   // (128, 64)
    enc_gemm_hmma<<<gGrid, 256>>>(xh, be, hsp);

    topk_kernel<<<M / 8, 256>>>(hsp, x, be);

    decoder_kernel<<<M, 256>>>(x, w0, w1, bd, xhat);

    finalize_kernel<<<1, 1>>>(scal);
}

// round 15
// speedup vs baseline: 1.5808x; 1.5808x over previous
#include <cuda_runtime.h>
#include <cuda_bf16.h>
#include <cuda_fp16.h>
#include <cstdint>
#include <cstddef>

// Problem sizes (fixed by the reference)
constexpr int M  = 8192;    // batch
constexpr int N  = 16384;   // d_sae
constexpr int KD = 1024;    // d_in
constexpr int TOPK = 32;
constexpr int NCAND = 48;   // candidate pool for exact refinement

// Output layout: [x_hat (M*KD), h_sparse (M*N), recon_loss, l0]
constexpr size_t OFF_H    = (size_t)M * KD;
constexpr size_t OFF_LOSS = OFF_H + (size_t)M * N;

// Scratch: control state + transposed W copies (96 MB total; proven-safe regime)
__device__ float g_val[M * TOPK];
__device__ int   g_idx[M * TOPK];
__device__ float g_loss_sum;
__device__ int   g_pos_count;
__device__ int   g_w0_is_enc;
__device__ __align__(16) __half g_wt_f16[(size_t)N * KD];   // 32 MB, W_enc^T [N][KD]
__device__ __align__(16) float  g_wt_f32[(size_t)N * KD];   // 64 MB, W_enc^T [N][KD]

// ---------------------------------------------------------------------------
// Helpers (sm_80-compatible PTX only: mma.sync + cp.async + ldmatrix)
// ---------------------------------------------------------------------------
__device__ __forceinline__ void mma_fp16(float* c, const uint32_t* a, const uint32_t* b) {
    asm volatile(
        "mma.sync.aligned.m16n8k16.row.col.f32.f16.f16.f32 "
        "{%0,%1,%2,%3}, {%4,%5,%6,%7}, {%8,%9}, {%0,%1,%2,%3};\n"
        : "+f"(c[0]), "+f"(c[1]), "+f"(c[2]), "+f"(c[3])
        : "r"(a[0]), "r"(a[1]), "r"(a[2]), "r"(a[3]), "r"(b[0]), "r"(b[1]));
}
__device__ __forceinline__ void cp_async16(uint32_t saddr, const void* gptr) {
    asm volatile("cp.async.ca.shared.global [%0], [%1], 16;" :: "r"(saddr), "l"(gptr));
}
#define CP_COMMIT()  asm volatile("cp.async.commit_group;" ::: "memory")
#define CP_WAIT(n)   asm volatile("cp.async.wait_group %0;" :: "n"(n) : "memory")
__device__ __forceinline__ void ldmx4(uint32_t* r, uint32_t addr) {
    asm volatile("ldmatrix.sync.aligned.m8n8.x4.shared.b16 {%0,%1,%2,%3}, [%4];"
        : "=r"(r[0]), "=r"(r[1]), "=r"(r[2]), "=r"(r[3]) : "r"(addr));
}

// ---------------------------------------------------------------------------
// Kernel D: decide which 16.7M tensor is W_enc; reset accumulators.
// ---------------------------------------------------------------------------
__global__ void detect_kernel(const float* __restrict__ w0,
                              const float* __restrict__ w1) {
    __shared__ float s0[256], s1[256];
    const int tid = threadIdx.x;
    float m0 = 0.f, m1 = 0.f;
    for (int i = tid; i < 8192; i += 256) {
        m0 = fmaxf(m0, fabsf(w0[i]));
        m1 = fmaxf(m1, fabsf(w1[i]));
    }
    s0[tid] = m0; s1[tid] = m1;
    __syncthreads();
    #pragma unroll
    for (int s = 128; s > 0; s >>= 1) {
        if (tid < s) {
            s0[tid] = fmaxf(s0[tid], s0[tid + s]);
            s1[tid] = fmaxf(s1[tid], s1[tid + s]);
        }
        __syncthreads();
    }
    if (tid == 0) {
        g_w0_is_enc = (s0[0] > s1[0]) ? 1 : 0;
        g_loss_sum  = 0.f;
        g_pos_count = 0;
    }
}

// ---------------------------------------------------------------------------
// Kernel C1: x fp32 -> fp16, stored in the x_hat region of d_out.
// ---------------------------------------------------------------------------
__global__ void convert_x_kernel(const float* __restrict__ x,
                                 __half* __restrict__ xh) {
    const size_t i = ((size_t)blockIdx.x * 256 + threadIdx.x) * 8;
    float4 v0 = *(const float4*)(x + i);
    float4 v1 = *(const float4*)(x + i + 4);
    __half2 h[4];
    h[0] = __floats2half2_rn(v0.x, v0.y);
    h[1] = __floats2half2_rn(v0.z, v0.w);
    h[2] = __floats2half2_rn(v1.x, v1.y);
    h[3] = __floats2half2_rn(v1.z, v1.w);
    *(uint4*)(xh + i) = *(uint4*)h;
}

// ---------------------------------------------------------------------------
// Kernel C2: transpose W_enc [KD][N] -> g_wt_f16 and g_wt_f32 [N][KD].
// ---------------------------------------------------------------------------
__global__ void convert_w_kernel(const float* __restrict__ W0,
                                 const float* __restrict__ W1) {
    __shared__ float tile[32][33];
    const float* __restrict__ W = g_w0_is_enc ? W0 : W1;   // W_enc [KD][N]
    const int n0 = blockIdx.x * 32;
    const int k0 = blockIdx.y * 32;
    const int tx = threadIdx.x & 31;
    const int ty = threadIdx.x >> 5;     // 0..7
    #pragma unroll
    for (int i = 0; i < 4; i++) {
        const int kr = ty + i * 8;
        tile[kr][tx] = W[(size_t)(k0 + kr) * N + n0 + tx];
    }
    __syncthreads();
    #pragma unroll
    for (int i = 0; i < 4; i++) {
        const int nr = ty + i * 8;
        const float f = tile[tx][nr];
        g_wt_f16[(size_t)(n0 + nr) * KD + k0 + tx] = __float2half_rn(f);
        g_wt_f32[(size_t)(n0 + nr) * KD + k0 + tx] = f;
    }
}

// ---------------------------------------------------------------------------
// Kernel 1: encoder GEMM, single-pass fp16 HMMA, fp32 accumulate.
// EXACT R12/R14 configuration (proven: 1.033 ms).
// ---------------------------------------------------------------------------
constexpr uint32_t SOFF_A = 0, SOFF_B = 6144;
constexpr uint32_t BUFSZ = 12288;

__global__ void __launch_bounds__(256, 2) enc_gemm_hmma(
    const __half* __restrict__ xh,   // [M][KD]
    const float* __restrict__ be,
    float* __restrict__ C)
{
    __shared__ __align__(16) uint8_t smraw[2 * BUFSZ];   // 24 KB static

    const int tid  = threadIdx.x;
    const int warp = tid >> 5;
    const int lane = tid & 31;
    const int g    = lane >> 2;
    const int t    = lane & 3;
    const int wm   = warp >> 2;
    const int wn   = warp & 3;
    const int rowBase = blockIdx.y * 128;
    const int colBase = blockIdx.x * 128;
    const uint32_t sb = (uint32_t)__cvta_generic_to_shared(smraw);

    const int ldrow = tid >> 1;
    const int ldseg = tid & 1;
    const uint32_t dstOff = (uint32_t)ldrow * 48 + (uint32_t)ldseg * 16;
    const size_t aSrc = (size_t)(rowBase + ldrow) * KD + ldseg * 8;
    const size_t bSrc = (size_t)(colBase + ldrow) * KD + ldseg * 8;

    const uint32_t aFragOff = (uint32_t)(wm * 64 + (lane & 15)) * 48 + ((lane >> 4) * 16);
    const uint32_t bFragOff = (uint32_t)(wn * 32 + (lane & 15)) * 48 + ((lane >> 4) * 16);

    float acc[4][4][4];
    #pragma unroll
    for (int i = 0; i < 4; i++)
        #pragma unroll
        for (int j = 0; j < 4; j++)
            #pragma unroll
            for (int e = 0; e < 4; e++) acc[i][j][e] = 0.f;

    auto issue = [&](int k0, int buf) {
        const uint32_t b = sb + (uint32_t)buf * BUFSZ;
        cp_async16(b + SOFF_A + dstOff, xh + aSrc + k0);
        cp_async16(b + SOFF_B + dstOff, g_wt_f16 + bSrc + k0);
        CP_COMMIT();
    };

    issue(0, 0);
    #pragma unroll 1
    for (int ic = 0; ic < KD / 16; ic++) {
        CP_WAIT(0);
        __syncthreads();
        if (ic < KD / 16 - 1)
            issue((ic + 1) * 16, (ic + 1) & 1);

        const uint32_t bb = sb + (uint32_t)(ic & 1) * BUFSZ;
        uint32_t ah[4][4], bh[2][4];
        #pragma unroll
        for (int mf = 0; mf < 4; mf++)
            ldmx4(ah[mf], bb + SOFF_A + aFragOff + mf * 768);
        #pragma unroll
        for (int b2 = 0; b2 < 2; b2++)
            ldmx4(bh[b2], bb + SOFF_B + bFragOff + b2 * 768);

        #pragma unroll
        for (int mf = 0; mf < 4; mf++) {
            #pragma unroll
            for (int b2 = 0; b2 < 2; b2++) {
                uint32_t b0[2] = { bh[b2][0], bh[b2][2] };
                uint32_t b1[2] = { bh[b2][1], bh[b2][3] };
                mma_fp16(acc[mf][2 * b2 + 0], ah[mf], b0);
                mma_fp16(acc[mf][2 * b2 + 1], ah[mf], b1);
            }
        }
    }

    #pragma unroll
    for (int mf = 0; mf < 4; mf++) {
        const int row = rowBase + wm * 64 + mf * 16 + g;
        #pragma unroll
        for (int b2 = 0; b2 < 2; b2++) {
            #pragma unroll
            for (int j = 0; j < 2; j++) {
                const int col = colBase + wn * 32 + b2 * 16 + j * 8 + 2 * t;
                const float* a = acc[mf][2 * b2 + j];
                const float2 bv = *(const float2*)(be + col);
                float2 o0, o1;
                o0.x = fmaxf(a[0] + bv.x, 0.f);
                o0.y = fmaxf(a[1] + bv.y, 0.f);
                o1.x = fmaxf(a[2] + bv.x, 0.f);
                o1.y = fmaxf(a[3] + bv.y, 0.f);
                *(float2*)(C + (size_t)row * N + col)       = o0;
                *(float2*)(C + (size_t)(row + 8) * N + col) = o1;
            }
        }
    }
}

// ---------------------------------------------------------------------------
// Kernel 2: per-row top-32, warp-per-row.
//  - Coalesced interleaved scan; per-lane TOP-2 in registers (2-compare insert)
//  - Extraction: 48 warp argmaxes over lane heads; pop shifts v2->v1.
//    Refill (lane held >=3 of top-48; ~0.65/row) = rare cooperative rescan for
//    the top-2 strictly after the lane's last-popped (v desc, idx asc).
//    No consume-stores to the row.
//  - Unconditional fp32 re-rank of the 48 candidates (float4 + 4 accumulators,
//    contiguous g_wt_f32 rows); refined values are STORED (rel_err ~3e-6).
//  - fp64 escalation only when refined gap(rank31, rank32) < 5e-4 (~3.7%).
//  - Zero row + scatter by rank.
// ---------------------------------------------------------------------------
__global__ __launch_bounds__(256) void topk_kernel(
    float* __restrict__ hsp,
    const float* __restrict__ x,
    const float* __restrict__ be)
{
    __shared__ int    s_ci[8][NCAND];
    __shared__ double s_rv[8][NCAND];
    __shared__ int    s_keep[8][TOPK];
    __shared__ float  s_gapv[8][2];

    const int w    = threadIdx.x >> 5;
    const int lane = threadIdx.x & 31;
    const int row  = blockIdx.x * 8 + w;
    float* pre = hsp + (size_t)row * N;

    // ---- scan: coalesced interleaved, per-lane top-2 ----
    float v1 = -1.f, v2 = -1.f; int i1 = 1 << 30, i2 = 1 << 30;
    #pragma unroll 4
    for (int j = 0; j < 128; j++) {
        const int gi = (j * 32 + lane) * 4;
        float4 v = *(const float4*)(pre + gi);
        const float vs[4] = { v.x, v.y, v.z, v.w };
        #pragma unroll
        for (int e = 0; e < 4; e++) {
            const float vv = vs[e]; const int ii = gi + e;
            if (vv > v2 || (vv == v2 && ii < i2)) {
                if (vv > v1 || (vv == v1 && ii < i1)) { v2 = v1; i2 = i1; v1 = vv; i1 = ii; }
                else                                  { v2 = vv; i2 = ii; }
            }
        }
    }

    // ---- extraction: 48 pops ----
    float lastV = 1e30f; int lastI = -1;
    for (int it = 0; it < NCAND; it++) {
        // refill lanes whose head is invalid (rare)
        unsigned need = __ballot_sync(0xffffffffu, v1 < -2.f);
        while (need) {
            const int rl = __ffs(need) - 1;
            need &= need - 1;
            const float lV = __shfl_sync(0xffffffffu, lastV, rl);
            const int   lI = __shfl_sync(0xffffffffu, lastI, rl);
            float nv1 = -1.f, nv2 = -1.f; int ni1 = 1 << 30, ni2 = 1 << 30;
            #pragma unroll
            for (int q = 0; q < 4; q++) {
                const int j  = lane * 4 + q;
                const int gi = (j * 32 + rl) * 4;
                float4 v = *(const float4*)(pre + gi);
                const float vs[4] = { v.x, v.y, v.z, v.w };
                #pragma unroll
                for (int e = 0; e < 4; e++) {
                    const float vv = vs[e]; const int ii = gi + e;
                    const bool after = (vv < lV) || (vv == lV && ii > lI);
                    if (after && (vv > nv2 || (vv == nv2 && ii < ni2))) {
                        if (vv > nv1 || (vv == nv1 && ii < ni1)) { nv2 = nv1; ni2 = ni1; nv1 = vv; ni1 = ii; }
                        else                                     { nv2 = vv; ni2 = ii; }
                    }
                }
            }
            // warp top-2 merge
            #pragma unroll
            for (int s = 16; s; s >>= 1) {
                float ov1 = __shfl_xor_sync(0xffffffffu, nv1, s);
                int   oi1 = __shfl_xor_sync(0xffffffffu, ni1, s);
                float ov2 = __shfl_xor_sync(0xffffffffu, nv2, s);
                int   oi2 = __shfl_xor_sync(0xffffffffu, ni2, s);
                const bool ogt = (ov1 > nv1) || (ov1 == nv1 && oi1 < ni1);
                const float a1 = ogt ? ov1 : nv1; const int a1i = ogt ? oi1 : ni1;
                const float b1 = ogt ? nv1 : ov1; const int b1i = ogt ? ni1 : oi1;
                const float c2 = ogt ? ov2 : nv2; const int c2i = ogt ? oi2 : ni2;
                const bool sg = (b1 > c2) || (b1 == c2 && b1i < c2i);
                nv1 = a1; ni1 = a1i;
                nv2 = sg ? b1 : c2; ni2 = sg ? b1i : c2i;
            }
            if (lane == rl) { v1 = nv1; i1 = ni1; v2 = nv2; i2 = ni2; }
        }

        // warp argmax over heads
        float bv = v1; int bi = i1;
        #pragma unroll
        for (int s = 16; s; s >>= 1) {
            float ov = __shfl_xor_sync(0xffffffffu, bv, s);
            int   oi = __shfl_xor_sync(0xffffffffu, bi, s);
            if (ov > bv || (ov == bv && oi < bi)) { bv = ov; bi = oi; }
        }
        if (lane == 0) s_ci[w][it] = bi;
        const int wl = (bi >> 2) & 31;
        if (lane == wl) {
            lastV = v1; lastI = i1;
            v1 = v2; i1 = i2;
            v2 = -3.f; i2 = 1 << 30;
        }
    }
    __syncwarp();

    // ---- unconditional fp32 re-rank of the 48 candidates ----
    const float* xr = x + (size_t)row * KD;
    for (int c = 0; c < NCAND; c++) {
        const int idx = s_ci[w][c];
        const float* wr = g_wt_f32 + (size_t)idx * KD;
        float s0 = 0.f, s1 = 0.f, s2 = 0.f, s3 = 0.f;
        #pragma unroll
        for (int q = 0; q < 8; q++) {
            const int k = (q * 32 + lane) * 4;
            float4 xv = *(const float4*)(xr + k);
            float4 wv = *(const float4*)(wr + k);
            s0 = fmaf(xv.x, wv.x, s0);
            s1 = fmaf(xv.y, wv.y, s1);
            s2 = fmaf(xv.z, wv.z, s2);
            s3 = fmaf(xv.w, wv.w, s3);
        }
        float s = (s0 + s1) + (s2 + s3);
        #pragma unroll
        for (int sh = 16; sh; sh >>= 1)
            s += __shfl_xor_sync(0xffffffffu, s, sh);
        if (lane == 0) s_rv[w][c] = (double)fmaxf(s + be[idx], 0.f);
    }
    __syncwarp();

    // ---- rank (parallel across lanes); fp64 escalation if boundary tight ----
    for (int pass = 0; pass < 2; pass++) {
        #pragma unroll
        for (int o = 0; o < 2; o++) {
            const int c = lane + o * 32;
            if (c < NCAND) {
                const double vc = s_rv[w][c];
                const int ic = s_ci[w][c];
                int r = 0;
                for (int d = 0; d < NCAND; d++) {
                    const double vd = s_rv[w][d];
                    if (vd > vc || (vd == vc && s_ci[w][d] < ic)) r++;
                }
                if (r < TOPK) s_keep[w][r] = c;
                if (r == TOPK - 1) s_gapv[w][0] = (float)vc;
                if (r == TOPK)     s_gapv[w][1] = (float)vc;
            }
        }
        __syncwarp();
        if (pass == 1) break;
        if (s_gapv[w][0] - s_gapv[w][1] >= 5e-4f) break;
        // fp64 recompute all 48 (rare: ~3.7% of rows)
        for (int c = 0; c < NCAND; c++) {
            const int idx = s_ci[w][c];
            const float* wr = g_wt_f32 + (size_t)idx * KD;
            double s = 0.0;
            for (int k = lane; k < KD; k += 32)
                s += (double)xr[k] * (double)wr[k];
            #pragma unroll
            for (int sh = 16; sh; sh >>= 1)
                s += __shfl_xor_sync(0xffffffffu, s, sh);
            if (lane == 0) s_rv[w][c] = fmax(s + (double)be[idx], 0.0);
        }
        __syncwarp();
    }
    __syncwarp();

    // ---- zero the row (coalesced), scatter the kept 32 by rank ----
    const float4 z4 = make_float4(0.f, 0.f, 0.f, 0.f);
    #pragma unroll 4
    for (int j = 0; j < 128; j++) {
        int gi = (j * 32 + lane) * 4;
        *(float4*)(pre + gi) = z4;
    }
    __syncwarp();
    float v = 0.f;
    if (lane < TOPK) {
        const int c = s_keep[w][lane];
        const int idx = s_ci[w][c];
        v = (float)s_rv[w][c];
        pre[idx] = v;
        g_val[row * TOPK + lane] = v;
        g_idx[row * TOPK + lane] = idx;
    }
    const unsigned posmask = __ballot_sync(0xffffffffu, (lane < TOPK) && (v > 0.f));
    if (lane == 0) atomicAdd(&g_pos_count, __popc(posmask));
}

// ---------------------------------------------------------------------------
// Kernel 3: sparse decoder + squared-error accumulation (unchanged)
// ---------------------------------------------------------------------------
__global__ __launch_bounds__(256) void decoder_kernel(
    const float* __restrict__ x,
    const float* __restrict__ W0,
    const float* __restrict__ W1,
    const float* __restrict__ bd,
    float* __restrict__ xhat)
{
    const float* __restrict__ Wd = g_w0_is_enc ? W1 : W0;   // W_dec [N, KD]

    __shared__ float sv[TOPK];
    __shared__ int   si[TOPK];
    __shared__ float red[256];

    const int row = blockIdx.x;
    const int tid = threadIdx.x;
    if (tid < TOPK) {
        sv[tid] = g_val[row * TOPK + tid];
        si[tid] = g_idx[row * TOPK + tid];
    }
    __syncthreads();

    const int d = tid * 4;
    float4 acc = *(const float4*)(bd + d);
    #pragma unroll 4
    for (int j = 0; j < TOPK; j++) {
        float v = sv[j];
        float4 wv = *(const float4*)(Wd + (size_t)si[j] * KD + d);
        acc.x = fmaf(v, wv.x, acc.x);
        acc.y = fmaf(v, wv.y, acc.y);
        acc.z = fmaf(v, wv.z, acc.z);
        acc.w = fmaf(v, wv.w, acc.w);
    }
    *(float4*)(xhat + (size_t)row * KD + d) = acc;

    float4 xv = *(const float4*)(x + (size_t)row * KD + d);
    float ex = acc.x - xv.x, ey = acc.y - xv.y;
    float ez = acc.z - xv.z, ew = acc.w - xv.w;
    red[tid] = ex * ex + ey * ey + ez * ez + ew * ew;
    __syncthreads();
    #pragma unroll
    for (int s = 128; s > 0; s >>= 1) {
        if (tid < s) red[tid] += red[tid + s];
        __syncthreads();
    }
    if (tid == 0) atomicAdd(&g_loss_sum, red[0]);
}

// ---------------------------------------------------------------------------
// Kernel 4: finalize scalars
// ---------------------------------------------------------------------------
__global__ void finalize_kernel(float* __restrict__ scal) {
    scal[0] = g_loss_sum / (float)((size_t)M * KD);
    scal[1] = (float)g_pos_count / (float)M;
}

// ---------------------------------------------------------------------------
extern "C" void kernel_launch(void* const* d_in, const int* in_sizes, int n_in,
                              void* d_out, int out_size) {
    const float* x  = nullptr;
    const float* be = nullptr;
    const float* bd = nullptr;
    const float* w0 = nullptr;
    const float* w1 = nullptr;
    for (int i = 0; i < n_in; i++) {
        const float* p = (const float*)d_in[i];
        const long long s = in_sizes[i];
        if      (s == (long long)M * KD || s == (long long)M * KD * 4) x  = p;
        else if (s == N        || s == (long long)N * 4)               be = p;
        else if (s == KD       || s == (long long)KD * 4)              bd = p;
        else if (s == (long long)KD * N || s == (long long)KD * N * 4) { if (!w0) w0 = p; else w1 = p; }
    }
    if (!x || !be || !bd || !w0 || !w1) {
        x  = (const float*)d_in[0];
        w0 = (const float*)d_in[1];
        be = (const float*)d_in[2];
        w1 = (const float*)d_in[3];
        bd = (const float*)d_in[4];
    }

    float* out  = (float*)d_out;
    float* xhat = out;
    float* hsp  = out + OFF_H;
    float* scal = out + OFF_LOSS;

    // x_f16 lives in the x_hat region until the decoder overwrites it
    __half* xh = (__half*)xhat;

    detect_kernel<<<1, 256>>>(w0, w1);

    convert_x_kernel<<<M * KD / 2048, 256>>>(x, xh);
    convert_w_kernel<<<dim3(N / 32, KD / 32), 256>>>(w0, w1);

    dim3 gGrid(N / 128, M / 128);   // (128, 64)
    enc_gemm_hmma<<<gGrid, 256>>>(xh, be, hsp);

    topk_kernel<<<M / 8, 256>>>(hsp, x, be);

    decoder_kernel<<<M, 256>>>(x, w0, w1, bd, xhat);

    finalize_kernel<<<1, 1>>>(scal);
}